// round 10
// baseline (speedup 1.0000x reference)
#include <cuda_runtime.h>
#include <cuda_bf16.h>
#include <math.h>

#define NB 128
#define NN 256
#define NSQ (NN*NN)
#define PP 32
#define KT 10
#define NPAIR 20
#define SWEEPS 7
#define QP 36
#define SPch 33
#define UPch 12

__device__ float g_A[(size_t)NB * NSQ];
__device__ float g_G[(size_t)NB * NSQ];

#define O_QS   0
#define O_YS   9216
#define O_PB   18432
#define O_SS   19584
#define O_VS   20640
#define O_VSEL 21696
#define O_US   22080
#define O_CS   25152
#define O_DS   27712
#define O_AVG  31808
#define O_MISC 32320
#define SMEM_FLOATS 32448
#define SMEM_BYTES (SMEM_FLOATS*4)

// y[t][:] = G(:,t)^T-weighted sum of Qin rows  (G symmetric: reads column t coalesced)
__device__ __forceinline__ void mv256(const float* __restrict__ Gb,
                                      const float* __restrict__ Qin,
                                      float* __restrict__ Yout, int t)
{
    float acc[PP];
#pragma unroll
    for (int j = 0; j < PP; j++) acc[j] = 0.f;
    const float* gp = Gb + t;
#pragma unroll 4
    for (int k = 0; k < NN; k++) {
        float g = __ldg(gp + (size_t)k * NN);
        const float4* qr = (const float4*)(Qin + k * QP);
#pragma unroll
        for (int j4 = 0; j4 < 8; j4++) {
            float4 q = qr[j4];
            acc[j4*4+0] = fmaf(g, q.x, acc[j4*4+0]);
            acc[j4*4+1] = fmaf(g, q.y, acc[j4*4+1]);
            acc[j4*4+2] = fmaf(g, q.z, acc[j4*4+2]);
            acc[j4*4+3] = fmaf(g, q.w, acc[j4*4+3]);
        }
    }
#pragma unroll
    for (int j4 = 0; j4 < 8; j4++)
        *(float4*)(Yout + t*QP + j4*4) =
            make_float4(acc[j4*4], acc[j4*4+1], acc[j4*4+2], acc[j4*4+3]);
}

// S[a][b] = sum_k X[k][a]*Y[k][b]
__device__ __forceinline__ void gram32(const float* __restrict__ X,
                                       const float* __restrict__ Y,
                                       float* __restrict__ S, int tid)
{
    int a = tid >> 3, b4 = (tid & 7) << 2;
    float s0=0.f, s1=0.f, s2=0.f, s3=0.f;
#pragma unroll 4
    for (int k = 0; k < NN; k++) {
        float xa = X[k*QP + a];
        float4 yb = *(const float4*)(Y + k*QP + b4);
        s0 = fmaf(xa, yb.x, s0); s1 = fmaf(xa, yb.y, s1);
        s2 = fmaf(xa, yb.z, s2); s3 = fmaf(xa, yb.w, s3);
    }
    S[a*SPch+b4+0]=s0; S[a*SPch+b4+1]=s1; S[a*SPch+b4+2]=s2; S[a*SPch+b4+3]=s3;
}

__device__ __forceinline__ void cholqr(float* __restrict__ Q, float* __restrict__ S,
                                       float* __restrict__ dinv, int tid)
{
    gram32(Q, Q, S, tid);
    __syncthreads();
    if (tid < 32) {
        int i = tid;
        for (int j = 0; j < 32; j++) {
            float d = sqrtf(fmaxf(S[j*SPch+j], 1e-30f));
            float lij = (i > j) ? S[i*SPch+j] / d : 0.f;
            __syncwarp();
            if (i == j) { S[j*SPch+j] = d; dinv[j] = 1.0f/d; }
            if (i >  j) S[i*SPch+j] = lij;
            __syncwarp();
            if (i > j)
                for (int c = j+1; c <= i; c++)
                    S[i*SPch+c] -= lij * S[c*SPch+j];
            __syncwarp();
        }
    }
    __syncthreads();
    float y[32], q[32];
#pragma unroll
    for (int j4 = 0; j4 < 8; j4++) {
        float4 v = *(const float4*)(Q + tid*QP + j4*4);
        y[j4*4]=v.x; y[j4*4+1]=v.y; y[j4*4+2]=v.z; y[j4*4+3]=v.w;
    }
#pragma unroll
    for (int j = 0; j < 32; j++) {
        float v = y[j];
#pragma unroll
        for (int i2 = 0; i2 < j; i2++) v -= q[i2] * S[j*SPch+i2];
        q[j] = v * dinv[j];
    }
#pragma unroll
    for (int j4 = 0; j4 < 8; j4++)
        *(float4*)(Q + tid*QP + j4*4) =
            make_float4(q[j4*4], q[j4*4+1], q[j4*4+2], q[j4*4+3]);
    __syncthreads();
}

__global__ void __launch_bounds__(256, 1)
cadzow_kernel(const float* __restrict__ Tin, const float* __restrict__ Tpin,
              const float* __restrict__ Spin, const float* __restrict__ w1,
              const float* __restrict__ w2,  const float* __restrict__ w3,
              const float* __restrict__ w4,  float* __restrict__ out)
{
    extern __shared__ float sm[];
    const int tid = threadIdx.x;
    const int b = blockIdx.x;

    float* Qs = sm + O_QS;  float* Ys = sm + O_YS;  float* Pc = sm + O_YS;
    float* Pb = sm + O_PB;  float* Ss = sm + O_SS;  float* Vs = sm + O_VS;
    float* Vsel = sm + O_VSEL; float* Us = sm + O_US; float* Cs = sm + O_CS;
    float* Ds = sm + O_DS;  float* Av = sm + O_AVG;
    float* cA = sm + O_MISC; float* sA = cA + 16;
    int* pA = (int*)(sA + 16); int* qA = pA + 16; int* idxS = qA + 16;
    float* dinv = (float*)(idxS + 16);

    float* Ab = g_A + (size_t)b * NSQ;
    float* Gb = g_G + (size_t)b * NSQ;
    const float* Tb  = Tin  + (size_t)b * NSQ;
    const float* Tpb = Tpin + (size_t)b * NSQ;
    const float* Spb = Spin + (size_t)b * NSQ;
    float* outT  = out;
    float* outTp = out + (size_t)NB * NSQ;
    float* outSp = out + 2*(size_t)NB * NSQ;

    // ---- Phase A: A = diag(w1)Sp + diag(w2)Tp + w4.*Tp + w3.*T ; copy T out ----
    for (int i = tid; i < NSQ; i += 256) {
        int r = i >> 8;
        float tv = Tb[i];
        Ab[i] = w1[r*257]*Spb[i] + (w2[r*257] + w4[i])*Tpb[i] + w3[i]*tv;
        outT[(size_t)b*NSQ + i] = tv;
    }
    __syncthreads();

    // ---- Phase B: G = A A^T (panel scheme) ----
    for (int jb = 0; jb < 8; jb++) {
        float acc[PP];
#pragma unroll
        for (int j = 0; j < PP; j++) acc[j] = 0.f;
        for (int kb = 0; kb < 8; kb++) {
            __syncthreads();
            for (int i = tid; i < NN*8; i += 256) {
                int r = i >> 3, c4 = i & 7;
                *(float4*)(Pc + r*QP + c4*4) =
                    *(const float4*)(Ab + r*NN + kb*PP + c4*4);
            }
            { int j = tid >> 3, c4 = tid & 7;
              *(float4*)(Pb + j*QP + c4*4) =
                  *(const float4*)(Ab + (jb*PP + j)*NN + kb*PP + c4*4); }
            __syncthreads();
#pragma unroll
            for (int c4 = 0; c4 < 8; c4++) {
                float4 own = *(const float4*)(Pc + tid*QP + c4*4);
#pragma unroll
                for (int j = 0; j < PP; j++) {
                    float4 bb = *(const float4*)(Pb + j*QP + c4*4);
                    acc[j] += own.x*bb.x + own.y*bb.y + own.z*bb.z + own.w*bb.w;
                }
            }
        }
#pragma unroll
        for (int c4 = 0; c4 < 8; c4++)
            *(float4*)(Gb + (size_t)tid*NN + jb*PP + c4*4) =
                make_float4(acc[c4*4], acc[c4*4+1], acc[c4*4+2], acc[c4*4+3]);
    }
    __syncthreads();

    // ---- Phase C: deterministic pseudo-random Q init ----
    for (int i = tid; i < NN*PP; i += 256) {
        int k = i >> 5, j = i & 31;
        unsigned h = (unsigned)(k*1664525 + j*1013904223 + 12345);
        h ^= h>>16; h *= 0x7feb352du; h ^= h>>15; h *= 0x846ca68bu; h ^= h>>16;
        Qs[k*QP + j] = (float)(h & 0xFFFFFFu) * (1.0f/8388608.0f) - 1.0f;
    }
    __syncthreads();

    // ---- Phase D: subspace iteration ----
    for (int p = 0; p < NPAIR; p++) {
        mv256(Gb, Qs, Ys, tid); __syncthreads();
        mv256(Gb, Ys, Qs, tid); __syncthreads();
        cholqr(Qs, Ss, dinv, tid);
    }
    mv256(Gb, Qs, Ys, tid);
    __syncthreads();

    // ---- Phase E: Rayleigh-Ritz ----
    gram32(Qs, Ys, Ss, tid);
    __syncthreads();
    for (int i = tid; i < 1024; i += 256) {
        int a2 = i >> 5, b2 = i & 31;
        Vs[a2*SPch + b2] = (a2 == b2) ? 1.0f : 0.f;
        if (a2 < b2) {
            float m = 0.5f*(Ss[a2*SPch+b2] + Ss[b2*SPch+a2]);
            Ss[a2*SPch+b2] = m; Ss[b2*SPch+a2] = m;
        }
    }
    __syncthreads();

    for (int sw = 0; sw < SWEEPS; sw++)
    for (int r = 0; r < 31; r++) {
        if (tid < 16) {
            int p2, q2;
            if (tid == 0) { p2 = 31; q2 = r % 31; }
            else { p2 = (r + tid) % 31; q2 = (r + 31 - tid) % 31; }
            float spp = Ss[p2*SPch+p2], sqq = Ss[q2*SPch+q2], spq = Ss[p2*SPch+q2];
            float c = 1.f, s = 0.f;
            if (fabsf(spq) > 1e-12f*(fabsf(spp)+fabsf(sqq)) + 1e-30f) {
                float tau = (sqq - spp) / (2.f*spq);
                float t2 = (tau >= 0.f ? 1.f : -1.f) / (fabsf(tau) + sqrtf(1.f + tau*tau));
                c = rsqrtf(1.f + t2*t2); s = t2*c;
            }
            cA[tid] = c; sA[tid] = s; pA[tid] = p2; qA[tid] = q2;
        }
        __syncthreads();
        for (int t2 = tid; t2 < 512; t2 += 256) {
            int k2 = t2 >> 5, row = t2 & 31;
            int p2 = pA[k2], q2 = qA[k2];
            float c = cA[k2], s = sA[k2];
            float a1 = Ss[row*SPch+p2], b1 = Ss[row*SPch+q2];
            Ss[row*SPch+p2] = c*a1 - s*b1;  Ss[row*SPch+q2] = s*a1 + c*b1;
            float v1 = Vs[row*SPch+p2], v2 = Vs[row*SPch+q2];
            Vs[row*SPch+p2] = c*v1 - s*v2;  Vs[row*SPch+q2] = s*v1 + c*v2;
        }
        __syncthreads();
        for (int t2 = tid; t2 < 512; t2 += 256) {
            int k2 = t2 >> 5, col = t2 & 31;
            int p2 = pA[k2], q2 = qA[k2];
            float c = cA[k2], s = sA[k2];
            float a1 = Ss[p2*SPch+col], b1 = Ss[q2*SPch+col];
            Ss[p2*SPch+col] = c*a1 - s*b1;  Ss[q2*SPch+col] = s*a1 + c*b1;
        }
        __syncthreads();
    }

    if (tid == 0) {
        float ev[32];
        for (int i2 = 0; i2 < 32; i2++) ev[i2] = Ss[i2*SPch+i2];
        for (int j = 0; j < KT; j++) {
            int bi = 0; float bv = -3.0e38f;
            for (int i2 = 0; i2 < 32; i2++) if (ev[i2] > bv) { bv = ev[i2]; bi = i2; }
            idxS[j] = bi; ev[bi] = -3.0e38f;
        }
    }
    __syncthreads();
    for (int i = tid; i < PP*UPch; i += 256) {
        int k2 = i % PP, j = i / PP;
        Vsel[k2*UPch + j] = (j < KT) ? Vs[k2*SPch + idxS[j]] : 0.f;
    }
    __syncthreads();

    // U = Q * Vsel  (256 x 10)
    {
        float u[KT];
#pragma unroll
        for (int j = 0; j < KT; j++) u[j] = 0.f;
#pragma unroll 4
        for (int k2 = 0; k2 < PP; k2++) {
            float qv = Qs[tid*QP + k2];
#pragma unroll
            for (int j = 0; j < KT; j++) u[j] = fmaf(qv, Vsel[k2*UPch + j], u[j]);
        }
#pragma unroll
        for (int j = 0; j < KT; j++) Us[tid*UPch + j] = u[j];
    }
    __syncthreads();

    // C = U^T A  (10 x 256): thread = column
    {
        float c[KT];
#pragma unroll
        for (int k = 0; k < KT; k++) c[k] = 0.f;
#pragma unroll 4
        for (int i = 0; i < NN; i++) {
            float a = __ldg(Ab + (size_t)i*NN + tid);
#pragma unroll
            for (int k = 0; k < KT; k++) c[k] = fmaf(Us[i*UPch + k], a, c[k]);
        }
#pragma unroll
        for (int k = 0; k < KT; k++) Cs[k*NN + tid] = c[k];
    }
    for (int i = tid; i < 4096; i += 256) Ds[i] = 0.f;
    __syncthreads();

    // Pass 1: Tpnew = U*C, write out, accumulate diagonal sums of 2*Tp - Sp
    {
        float creg[KT];
#pragma unroll
        for (int k = 0; k < KT; k++) creg[k] = Cs[k*NN + tid];
        float* dw = Ds + (tid >> 5)*512;
        for (int i = 0; i < NN; i++) {
            float tp = 0.f;
#pragma unroll
            for (int k = 0; k < KT; k++) tp = fmaf(Us[i*UPch + k], creg[k], tp);
            outTp[(size_t)b*NSQ + i*NN + tid] = tp;
            float m = 2.f*tp - __ldg(Spb + i*NN + tid);
            dw[tid - i + 255] += m;
        }
    }
    __syncthreads();
    for (int d = tid; d < 511; d += 256) {
        float s = 0.f;
#pragma unroll
        for (int w = 0; w < 8; w++) s += Ds[w*512 + d];
        int cnt = 256 - abs(d - 255);
        Av[d] = s / (float)cnt;
    }
    __syncthreads();

    // Pass 2: Spnew = Sp - Tpnew + avg[diag]
    for (int i = 0; i < NN; i++) {
        float tp = outTp[(size_t)b*NSQ + i*NN + tid];
        outSp[(size_t)b*NSQ + i*NN + tid] =
            __ldg(Spb + i*NN + tid) - tp + Av[tid - i + 255];
    }
}

extern "C" void kernel_launch(void* const* d_in, const int* in_sizes, int n_in,
                              void* d_out, int out_size) {
    const float* T  = (const float*)d_in[0];
    const float* Tp = (const float*)d_in[1];
    const float* Sp = (const float*)d_in[2];
    const float* w1 = (const float*)d_in[3];
    const float* w2 = (const float*)d_in[4];
    const float* w3 = (const float*)d_in[5];
    const float* w4 = (const float*)d_in[6];
    float* out = (float*)d_out;
    cudaFuncSetAttribute(cadzow_kernel,
                         cudaFuncAttributeMaxDynamicSharedMemorySize, SMEM_BYTES);
    cadzow_kernel<<<NB, 256, SMEM_BYTES>>>(T, Tp, Sp, w1, w2, w3, w4, out);
}

// round 14
// speedup vs baseline: 1.5976x; 1.5976x over previous
#include <cuda_runtime.h>
#include <cuda_bf16.h>
#include <math.h>

#define NB 128
#define NN 256
#define NSQ (NN*NN)
#define PP 32
#define KT 10
#define NPAIR 12
#define SWEEPS 7
#define QP 36
#define SPch 33
#define UPch 12
#define NT 512

__device__ float g_A[(size_t)NB * NSQ];
__device__ float g_G[(size_t)NB * NSQ];

#define O_QS   0
#define O_YS   9216
#define O_PB   18432
#define O_SS   19584
#define O_VS   20640
#define O_VSEL 21696
#define O_US   22080
#define O_CS   25152
#define O_AVG  30272
#define O_MISC 30784
#define SMEM_FLOATS 30912
#define SMEM_BYTES (SMEM_FLOATS*4)

// thread (t = tid&255, h = tid>>8) computes Y[t][h*16 .. h*16+16)
__device__ __forceinline__ void mv512(const float* __restrict__ Gb,
                                      const float* __restrict__ Qin,
                                      float* __restrict__ Yout, int t, int h)
{
    float acc[16];
#pragma unroll
    for (int j = 0; j < 16; j++) acc[j] = 0.f;
    const float* gp = Gb + t;
    const float* qb = Qin + h * 16;
#pragma unroll 4
    for (int k = 0; k < NN; k++) {
        float g = __ldg(gp + (size_t)k * NN);
        const float4* qr = (const float4*)(qb + k * QP);
#pragma unroll
        for (int c4 = 0; c4 < 4; c4++) {
            float4 q = qr[c4];
            acc[c4*4+0] = fmaf(g, q.x, acc[c4*4+0]);
            acc[c4*4+1] = fmaf(g, q.y, acc[c4*4+1]);
            acc[c4*4+2] = fmaf(g, q.z, acc[c4*4+2]);
            acc[c4*4+3] = fmaf(g, q.w, acc[c4*4+3]);
        }
    }
#pragma unroll
    for (int c4 = 0; c4 < 4; c4++)
        *(float4*)(Yout + t*QP + h*16 + c4*4) =
            make_float4(acc[c4*4], acc[c4*4+1], acc[c4*4+2], acc[c4*4+3]);
}

// S[a][b] = sum_k X[k][a]*Y[k][b] ; 512 threads, 2 outputs each
__device__ __forceinline__ void gram512(const float* __restrict__ X,
                                        const float* __restrict__ Y,
                                        float* __restrict__ S, int tid)
{
    int a = tid >> 4, b2 = (tid & 15) << 1;
    float s0 = 0.f, s1 = 0.f;
#pragma unroll 4
    for (int k = 0; k < NN; k++) {
        float xa = X[k*QP + a];
        float2 yb = *(const float2*)(Y + k*QP + b2);
        s0 = fmaf(xa, yb.x, s0);
        s1 = fmaf(xa, yb.y, s1);
    }
    S[a*SPch + b2]     = s0;
    S[a*SPch + b2 + 1] = s1;
}

__device__ __forceinline__ void cholqr512(float* __restrict__ Q, float* __restrict__ S,
                                          float* __restrict__ dinv, int tid)
{
    gram512(Q, Q, S, tid);
    __syncthreads();
    if (tid < 32) {
        int i = tid;
        for (int j = 0; j < 32; j++) {
            float d = sqrtf(fmaxf(S[j*SPch+j], 1e-30f));
            float lij = (i > j) ? S[i*SPch+j] / d : 0.f;
            __syncwarp();
            if (i == j) { S[j*SPch+j] = d; dinv[j] = 1.0f/d; }
            if (i >  j) S[i*SPch+j] = lij;
            __syncwarp();
            if (i > j)
                for (int c = j+1; c <= i; c++)
                    S[i*SPch+c] -= lij * S[c*SPch+j];
            __syncwarp();
        }
    }
    __syncthreads();
    if (tid < 256) {
        float q[32];
#pragma unroll
        for (int j = 0; j < 32; j++) {
            float v = Q[tid*QP + j];
#pragma unroll
            for (int i2 = 0; i2 < j; i2++) v -= q[i2] * S[j*SPch + i2];
            q[j] = v * dinv[j];
        }
#pragma unroll
        for (int j4 = 0; j4 < 8; j4++)
            *(float4*)(Q + tid*QP + j4*4) =
                make_float4(q[j4*4], q[j4*4+1], q[j4*4+2], q[j4*4+3]);
    }
    __syncthreads();
}

__global__ void __launch_bounds__(NT, 1)
cadzow_kernel(const float* __restrict__ Tin, const float* __restrict__ Tpin,
              const float* __restrict__ Spin, const float* __restrict__ w1,
              const float* __restrict__ w2,  const float* __restrict__ w3,
              const float* __restrict__ w4,  float* __restrict__ out)
{
    extern __shared__ float sm[];
    const int tid = threadIdx.x;
    const int b = blockIdx.x;
    const int t = tid & 255;
    const int h = tid >> 8;

    float* Qs = sm + O_QS;   float* Ys = sm + O_YS;  float* Pc = sm + O_YS;
    float* Pb = sm + O_PB;   float* Ss = sm + O_SS;  float* Vs = sm + O_VS;
    float* Vsel = sm + O_VSEL; float* Us = sm + O_US; float* Cs = sm + O_CS;
    float* Av = sm + O_AVG;
    float* cA = sm + O_MISC; float* sA = cA + 16;
    int* pA = (int*)(sA + 16); int* qA = pA + 16; int* idxS = qA + 16;
    float* dinv = (float*)(idxS + 16);

    float* Ab = g_A + (size_t)b * NSQ;
    float* Gb = g_G + (size_t)b * NSQ;
    const float* Tb  = Tin  + (size_t)b * NSQ;
    const float* Tpb = Tpin + (size_t)b * NSQ;
    const float* Spb = Spin + (size_t)b * NSQ;
    float* outT  = out + (size_t)b * NSQ;
    float* outTp = out + (size_t)NB * NSQ     + (size_t)b * NSQ;
    float* outSp = out + 2*(size_t)NB * NSQ   + (size_t)b * NSQ;

    // ---- Phase A: A = diag(w1)Sp + diag(w2)Tp + w4.*Tp + w3.*T ; copy T ----
    for (int i = tid; i < NSQ; i += NT) {
        int r = i >> 8;
        float tv = Tb[i];
        Ab[i] = w1[r*257]*Spb[i] + (w2[r*257] + w4[i])*Tpb[i] + w3[i]*tv;
        outT[i] = tv;
    }
    __syncthreads();

    // ---- Phase B: G = A A^T ; thread (t,h) computes G[t][jb*32 + h*16 .. +16) ----
    for (int jb = 0; jb < 8; jb++) {
        float acc[16];
#pragma unroll
        for (int j = 0; j < 16; j++) acc[j] = 0.f;
        for (int kb = 0; kb < 8; kb++) {
            __syncthreads();
            for (int i = tid; i < NN*8; i += NT) {
                int r = i >> 3, c4 = i & 7;
                *(float4*)(Pc + r*QP + c4*4) =
                    *(const float4*)(Ab + r*NN + kb*PP + c4*4);
            }
            if (tid < 256) {
                int j = tid >> 3, c4 = tid & 7;
                *(float4*)(Pb + j*QP + c4*4) =
                    *(const float4*)(Ab + (jb*PP + j)*NN + kb*PP + c4*4);
            }
            __syncthreads();
#pragma unroll
            for (int c4 = 0; c4 < 8; c4++) {
                float4 own = *(const float4*)(Pc + t*QP + c4*4);
#pragma unroll
                for (int j = 0; j < 16; j++) {
                    float4 bb = *(const float4*)(Pb + (h*16 + j)*QP + c4*4);
                    acc[j] += own.x*bb.x + own.y*bb.y + own.z*bb.z + own.w*bb.w;
                }
            }
        }
#pragma unroll
        for (int j4 = 0; j4 < 4; j4++)
            *(float4*)(Gb + (size_t)t*NN + jb*PP + h*16 + j4*4) =
                make_float4(acc[j4*4], acc[j4*4+1], acc[j4*4+2], acc[j4*4+3]);
    }
    __syncthreads();

    // ---- Phase C: deterministic pseudo-random Q init ----
    for (int i = tid; i < NN*PP; i += NT) {
        int k = i >> 5, j = i & 31;
        unsigned hh = (unsigned)(k*1664525 + j*1013904223 + 12345);
        hh ^= hh>>16; hh *= 0x7feb352du; hh ^= hh>>15; hh *= 0x846ca68bu; hh ^= hh>>16;
        Qs[k*QP + j] = (float)(hh & 0xFFFFFFu) * (1.0f/8388608.0f) - 1.0f;
    }
    __syncthreads();

    // ---- Phase D: subspace iteration ----
    for (int p = 0; p < NPAIR; p++) {
        mv512(Gb, Qs, Ys, t, h); __syncthreads();
        mv512(Gb, Ys, Qs, t, h); __syncthreads();
        cholqr512(Qs, Ss, dinv, tid);
    }
    mv512(Gb, Qs, Ys, t, h);
    __syncthreads();

    // ---- Phase E: Rayleigh-Ritz ----
    gram512(Qs, Ys, Ss, tid);
    __syncthreads();
    for (int i = tid; i < 1024; i += NT) {
        int a2 = i >> 5, b2 = i & 31;
        Vs[a2*SPch + b2] = (a2 == b2) ? 1.0f : 0.f;
        if (a2 < b2) {
            float m = 0.5f*(Ss[a2*SPch+b2] + Ss[b2*SPch+a2]);
            Ss[a2*SPch+b2] = m; Ss[b2*SPch+a2] = m;
        }
    }
    __syncthreads();

    for (int sw = 0; sw < SWEEPS; sw++)
    for (int r = 0; r < 31; r++) {
        if (tid < 16) {
            int p2, q2;
            if (tid == 0) { p2 = 31; q2 = r % 31; }
            else { p2 = (r + tid) % 31; q2 = (r + 31 - tid) % 31; }
            float spp = Ss[p2*SPch+p2], sqq = Ss[q2*SPch+q2], spq = Ss[p2*SPch+q2];
            float c = 1.f, s = 0.f;
            if (fabsf(spq) > 1e-12f*(fabsf(spp)+fabsf(sqq)) + 1e-30f) {
                float tau = (sqq - spp) / (2.f*spq);
                float t2 = (tau >= 0.f ? 1.f : -1.f) / (fabsf(tau) + sqrtf(1.f + tau*tau));
                c = rsqrtf(1.f + t2*t2); s = t2*c;
            }
            cA[tid] = c; sA[tid] = s; pA[tid] = p2; qA[tid] = q2;
        }
        __syncthreads();
        {   // column rotations on S and V (one element per thread)
            int k2 = tid >> 5, row = tid & 31;
            int p2 = pA[k2], q2 = qA[k2];
            float c = cA[k2], s = sA[k2];
            float a1 = Ss[row*SPch+p2], b1 = Ss[row*SPch+q2];
            Ss[row*SPch+p2] = c*a1 - s*b1;  Ss[row*SPch+q2] = s*a1 + c*b1;
            float v1 = Vs[row*SPch+p2], v2 = Vs[row*SPch+q2];
            Vs[row*SPch+p2] = c*v1 - s*v2;  Vs[row*SPch+q2] = s*v1 + c*v2;
        }
        __syncthreads();
        {   // row rotations on S
            int k2 = tid >> 5, col = tid & 31;
            int p2 = pA[k2], q2 = qA[k2];
            float c = cA[k2], s = sA[k2];
            float a1 = Ss[p2*SPch+col], b1 = Ss[q2*SPch+col];
            Ss[p2*SPch+col] = c*a1 - s*b1;  Ss[q2*SPch+col] = s*a1 + c*b1;
        }
        __syncthreads();
    }

    if (tid == 0) {
        float ev[32];
        for (int i2 = 0; i2 < 32; i2++) ev[i2] = Ss[i2*SPch+i2];
        for (int j = 0; j < KT; j++) {
            int bi = 0; float bv = -3.0e38f;
            for (int i2 = 0; i2 < 32; i2++) if (ev[i2] > bv) { bv = ev[i2]; bi = i2; }
            idxS[j] = bi; ev[bi] = -3.0e38f;
        }
    }
    __syncthreads();
    if (tid < PP*UPch) {
        int k2 = tid % PP, j = tid / PP;
        Vsel[k2*UPch + j] = (j < KT) ? Vs[k2*SPch + idxS[j]] : 0.f;
    }
    __syncthreads();

    // U = Q * Vsel  (256 x 10)
    if (tid < 256) {
        float u[KT];
#pragma unroll
        for (int j = 0; j < KT; j++) u[j] = 0.f;
#pragma unroll 4
        for (int k2 = 0; k2 < PP; k2++) {
            float qv = Qs[tid*QP + k2];
#pragma unroll
            for (int j = 0; j < KT; j++) u[j] = fmaf(qv, Vsel[k2*UPch + j], u[j]);
        }
#pragma unroll
        for (int j = 0; j < KT; j++) Us[tid*UPch + j] = u[j];
    }
    __syncthreads();

    // C = U^T A  (10 x 256) split over halves, partials in Cs
    {
        float c[KT];
#pragma unroll
        for (int k = 0; k < KT; k++) c[k] = 0.f;
        int i0 = h * 128;
#pragma unroll 4
        for (int i = i0; i < i0 + 128; i++) {
            float a = __ldg(Ab + (size_t)i*NN + t);
#pragma unroll
            for (int k = 0; k < KT; k++) c[k] = fmaf(Us[i*UPch + k], a, c[k]);
        }
#pragma unroll
        for (int k = 0; k < KT; k++) Cs[h*2560 + k*NN + t] = c[k];
    }
    __syncthreads();

    // Pass 1: Tpnew = U*C, write out
    float creg[KT];
#pragma unroll
    for (int k = 0; k < KT; k++) creg[k] = Cs[k*NN + t] + Cs[2560 + k*NN + t];
    {
        int i0 = h * 128;
        for (int i = i0; i < i0 + 128; i++) {
            float tp = 0.f;
#pragma unroll
            for (int k = 0; k < KT; k++) tp = fmaf(Us[i*UPch + k], creg[k], tp);
            outTp[(size_t)i*NN + t] = tp;
        }
    }
    __syncthreads();

    // Diagonal averages of M = 2*Tpnew - Sp: one thread per diagonal.
    // d = col - row + 255; entries (i, j=i+d-255). Coalesced: lane-consecutive j.
    if (tid < 511) {
        int off = tid - 255;
        float s = 0.f;
        for (int i = 0; i < NN; i++) {
            int j = i + off;
            if ((unsigned)j < NN) {
                float tp = outTp[(size_t)i*NN + j];   // same-CTA write, visible after barrier
                float sp = Spb[(size_t)i*NN + j];
                s += 2.f*tp - sp;
            }
        }
        int cnt = NN - abs(off);
        Av[tid] = s / (float)cnt;
    }
    __syncthreads();

    // Pass 2: Spnew = Sp - Tpnew + avg[diag]  (recompute tp from registers)
    {
        int i0 = h * 128;
        for (int i = i0; i < i0 + 128; i++) {
            float tp = 0.f;
#pragma unroll
            for (int k = 0; k < KT; k++) tp = fmaf(Us[i*UPch + k], creg[k], tp);
            outSp[(size_t)i*NN + t] =
                __ldg(Spb + (size_t)i*NN + t) - tp + Av[t - i + 255];
        }
    }
}

extern "C" void kernel_launch(void* const* d_in, const int* in_sizes, int n_in,
                              void* d_out, int out_size) {
    const float* T  = (const float*)d_in[0];
    const float* Tp = (const float*)d_in[1];
    const float* Sp = (const float*)d_in[2];
    const float* w1 = (const float*)d_in[3];
    const float* w2 = (const float*)d_in[4];
    const float* w3 = (const float*)d_in[5];
    const float* w4 = (const float*)d_in[6];
    float* out = (float*)d_out;
    cudaFuncSetAttribute(cadzow_kernel,
                         cudaFuncAttributeMaxDynamicSharedMemorySize, SMEM_BYTES);
    cadzow_kernel<<<NB, NT, SMEM_BYTES>>>(T, Tp, Sp, w1, w2, w3, w4, out);
}

// round 16
// speedup vs baseline: 1.6474x; 1.0312x over previous
#include <cuda_runtime.h>
#include <cuda_bf16.h>
#include <math.h>

#define NB 128
#define NN 256
#define NSQ (NN*NN)
#define PP 32
#define KT 10
#define NSTAGE 7          // 7 stages x 4 matvecs = 28 power iterations
#define SWEEPS 7
#define QP 36
#define SPch 33
#define UPch 12
#define NT 512

__device__ float g_A[(size_t)NB * NSQ];
__device__ float g_G[(size_t)NB * NSQ];

#define O_QS   0
#define O_YS   9216
#define O_PB   18432
#define O_SS   19584
#define O_VS   20640
#define O_VSEL 21696
#define O_US   22080
#define O_CS   25152
#define O_AVG  30272
#define O_MISC 30784
#define O_SG   30912            /* 2 x 2048 floats: staged G rows */
#define SMEM_FLOATS (O_SG + 4096)
#define SMEM_BYTES (SMEM_FLOATS*4)   /* 140,032 B */

// Y = G * Qin (256x256 * 256x32). thread (t,h) -> Y[t][h*16..h*16+16).
// G rows streamed through double-buffered smem; one float4 LDG prefetch per
// thread per group overlaps the group's 1024-cyc FFMA consumption.
__device__ __forceinline__ void mv512s(const float* __restrict__ Gb,
                                       const float* __restrict__ Qin,
                                       float* __restrict__ Yout,
                                       float* __restrict__ sG,
                                       int t, int h, int tid)
{
    float acc[16];
#pragma unroll
    for (int j = 0; j < 16; j++) acc[j] = 0.f;
    const float* qb = Qin + h * 16;

    // prologue: rows 0..7 -> buffer 0 (512 threads x 1 float4 = 2048 floats)
    ((float4*)sG)[tid] = __ldg((const float4*)Gb + tid);
    __syncthreads();

    for (int grp = 0; grp < 32; grp++) {
        const float* cur = sG + (grp & 1) * 2048;
        float*       nxt = sG + ((grp & 1) ^ 1) * 2048;
        float4 pre;
        const bool havepre = (grp + 1 < 32);
        if (havepre)
            pre = __ldg((const float4*)(Gb + (size_t)(grp + 1) * 2048) + tid);
#pragma unroll
        for (int u = 0; u < 8; u++) {
            float g = cur[u*NN + t];
            const float4* qr = (const float4*)(qb + (grp*8 + u) * QP);
#pragma unroll
            for (int c4 = 0; c4 < 4; c4++) {
                float4 q = qr[c4];
                acc[c4*4+0] = fmaf(g, q.x, acc[c4*4+0]);
                acc[c4*4+1] = fmaf(g, q.y, acc[c4*4+1]);
                acc[c4*4+2] = fmaf(g, q.z, acc[c4*4+2]);
                acc[c4*4+3] = fmaf(g, q.w, acc[c4*4+3]);
            }
        }
        if (havepre) ((float4*)nxt)[tid] = pre;
        __syncthreads();
    }
#pragma unroll
    for (int c4 = 0; c4 < 4; c4++)
        *(float4*)(Yout + t*QP + h*16 + c4*4) =
            make_float4(acc[c4*4], acc[c4*4+1], acc[c4*4+2], acc[c4*4+3]);
}

// S[a][b] = sum_k X[k][a]*Y[k][b] ; 512 threads, 2 outputs each
__device__ __forceinline__ void gram512(const float* __restrict__ X,
                                        const float* __restrict__ Y,
                                        float* __restrict__ S, int tid)
{
    int a = tid >> 4, b2 = (tid & 15) << 1;
    float s0 = 0.f, s1 = 0.f;
#pragma unroll 4
    for (int k = 0; k < NN; k++) {
        float xa = X[k*QP + a];
        float2 yb = *(const float2*)(Y + k*QP + b2);
        s0 = fmaf(xa, yb.x, s0);
        s1 = fmaf(xa, yb.y, s1);
    }
    S[a*SPch + b2]     = s0;
    S[a*SPch + b2 + 1] = s1;
}

__device__ __forceinline__ void cholqr512(float* __restrict__ Q, float* __restrict__ S,
                                          float* __restrict__ dinv, int tid)
{
    gram512(Q, Q, S, tid);
    __syncthreads();
    if (tid < 32) {
        int i = tid;
        for (int j = 0; j < 32; j++) {
            float d = sqrtf(fmaxf(S[j*SPch+j], 1e-30f));
            float lij = (i > j) ? S[i*SPch+j] / d : 0.f;
            __syncwarp();
            if (i == j) { S[j*SPch+j] = d; dinv[j] = 1.0f/d; }
            if (i >  j) S[i*SPch+j] = lij;
            __syncwarp();
            if (i > j)
                for (int c = j+1; c <= i; c++)
                    S[i*SPch+c] -= lij * S[c*SPch+j];
            __syncwarp();
        }
    }
    __syncthreads();
    if (tid < 256) {
        float q[32];
#pragma unroll
        for (int j = 0; j < 32; j++) {
            float v = Q[tid*QP + j];
#pragma unroll
            for (int i2 = 0; i2 < j; i2++) v -= q[i2] * S[j*SPch + i2];
            q[j] = v * dinv[j];
        }
#pragma unroll
        for (int j4 = 0; j4 < 8; j4++)
            *(float4*)(Q + tid*QP + j4*4) =
                make_float4(q[j4*4], q[j4*4+1], q[j4*4+2], q[j4*4+3]);
    }
    __syncthreads();
}

__global__ void __launch_bounds__(NT, 1)
cadzow_kernel(const float* __restrict__ Tin, const float* __restrict__ Tpin,
              const float* __restrict__ Spin, const float* __restrict__ w1,
              const float* __restrict__ w2,  const float* __restrict__ w3,
              const float* __restrict__ w4,  float* __restrict__ out)
{
    extern __shared__ float sm[];
    const int tid = threadIdx.x;
    const int b = blockIdx.x;
    const int t = tid & 255;
    const int h = tid >> 8;

    float* Qs = sm + O_QS;   float* Ys = sm + O_YS;  float* Pc = sm + O_YS;
    float* Pb = sm + O_PB;   float* Ss = sm + O_SS;  float* Vs = sm + O_VS;
    float* Vsel = sm + O_VSEL; float* Us = sm + O_US; float* Cs = sm + O_CS;
    float* Av = sm + O_AVG;  float* sG = sm + O_SG;
    float* cA = sm + O_MISC; float* sA = cA + 16;
    int* pA = (int*)(sA + 16); int* qA = pA + 16; int* idxS = qA + 16;
    float* dinv = (float*)(idxS + 16);

    float* Ab = g_A + (size_t)b * NSQ;
    float* Gb = g_G + (size_t)b * NSQ;
    const float* Tb  = Tin  + (size_t)b * NSQ;
    const float* Tpb = Tpin + (size_t)b * NSQ;
    const float* Spb = Spin + (size_t)b * NSQ;
    float* outT  = out + (size_t)b * NSQ;
    float* outTp = out + (size_t)NB * NSQ     + (size_t)b * NSQ;
    float* outSp = out + 2*(size_t)NB * NSQ   + (size_t)b * NSQ;

    // ---- Phase A: A = diag(w1)Sp + diag(w2)Tp + w4.*Tp + w3.*T ; copy T ----
    for (int i = tid; i < NSQ; i += NT) {
        int r = i >> 8;
        float tv = Tb[i];
        Ab[i] = w1[r*257]*Spb[i] + (w2[r*257] + w4[i])*Tpb[i] + w3[i]*tv;
        outT[i] = tv;
    }
    __syncthreads();

    // ---- Phase B: G = A A^T ; thread (t,h) computes G[t][jb*32 + h*16 .. +16) ----
    for (int jb = 0; jb < 8; jb++) {
        float acc[16];
#pragma unroll
        for (int j = 0; j < 16; j++) acc[j] = 0.f;
        for (int kb = 0; kb < 8; kb++) {
            __syncthreads();
            for (int i = tid; i < NN*8; i += NT) {
                int r = i >> 3, c4 = i & 7;
                *(float4*)(Pc + r*QP + c4*4) =
                    *(const float4*)(Ab + r*NN + kb*PP + c4*4);
            }
            if (tid < 256) {
                int j = tid >> 3, c4 = tid & 7;
                *(float4*)(Pb + j*QP + c4*4) =
                    *(const float4*)(Ab + (jb*PP + j)*NN + kb*PP + c4*4);
            }
            __syncthreads();
#pragma unroll
            for (int c4 = 0; c4 < 8; c4++) {
                float4 own = *(const float4*)(Pc + t*QP + c4*4);
#pragma unroll
                for (int j = 0; j < 16; j++) {
                    float4 bb = *(const float4*)(Pb + (h*16 + j)*QP + c4*4);
                    acc[j] += own.x*bb.x + own.y*bb.y + own.z*bb.z + own.w*bb.w;
                }
            }
        }
#pragma unroll
        for (int j4 = 0; j4 < 4; j4++)
            *(float4*)(Gb + (size_t)t*NN + jb*PP + h*16 + j4*4) =
                make_float4(acc[j4*4], acc[j4*4+1], acc[j4*4+2], acc[j4*4+3]);
    }
    __syncthreads();

    // ---- Phase C: deterministic pseudo-random Q init ----
    for (int i = tid; i < NN*PP; i += NT) {
        int k = i >> 5, j = i & 31;
        unsigned hh = (unsigned)(k*1664525 + j*1013904223 + 12345);
        hh ^= hh>>16; hh *= 0x7feb352du; hh ^= hh>>15; hh *= 0x846ca68bu; hh ^= hh>>16;
        Qs[k*QP + j] = (float)(hh & 0xFFFFFFu) * (1.0f/8388608.0f) - 1.0f;
    }
    __syncthreads();

    // ---- Phase D: 7 x (4 matvecs + CholQR) = 28 power iterations ----
    for (int st = 0; st < NSTAGE; st++) {
        mv512s(Gb, Qs, Ys, sG, t, h, tid); __syncthreads();
        mv512s(Gb, Ys, Qs, sG, t, h, tid); __syncthreads();
        mv512s(Gb, Qs, Ys, sG, t, h, tid); __syncthreads();
        mv512s(Gb, Ys, Qs, sG, t, h, tid); __syncthreads();
        cholqr512(Qs, Ss, dinv, tid);
    }
    mv512s(Gb, Qs, Ys, sG, t, h, tid);   // final Y = G*Q for Rayleigh-Ritz
    __syncthreads();

    // ---- Phase E: Rayleigh-Ritz ----
    gram512(Qs, Ys, Ss, tid);
    __syncthreads();
    for (int i = tid; i < 1024; i += NT) {
        int a2 = i >> 5, b2 = i & 31;
        Vs[a2*SPch + b2] = (a2 == b2) ? 1.0f : 0.f;
        if (a2 < b2) {
            float m = 0.5f*(Ss[a2*SPch+b2] + Ss[b2*SPch+a2]);
            Ss[a2*SPch+b2] = m; Ss[b2*SPch+a2] = m;
        }
    }
    __syncthreads();

    for (int sw = 0; sw < SWEEPS; sw++)
    for (int r = 0; r < 31; r++) {
        if (tid < 16) {
            int p2, q2;
            if (tid == 0) { p2 = 31; q2 = r % 31; }
            else { p2 = (r + tid) % 31; q2 = (r + 31 - tid) % 31; }
            float spp = Ss[p2*SPch+p2], sqq = Ss[q2*SPch+q2], spq = Ss[p2*SPch+q2];
            float c = 1.f, s = 0.f;
            if (fabsf(spq) > 1e-12f*(fabsf(spp)+fabsf(sqq)) + 1e-30f) {
                float tau = (sqq - spp) / (2.f*spq);
                float t2 = (tau >= 0.f ? 1.f : -1.f) / (fabsf(tau) + sqrtf(1.f + tau*tau));
                c = rsqrtf(1.f + t2*t2); s = t2*c;
            }
            cA[tid] = c; sA[tid] = s; pA[tid] = p2; qA[tid] = q2;
        }
        __syncthreads();
        {   // column rotations on S and V (one element per thread)
            int k2 = tid >> 5, row = tid & 31;
            int p2 = pA[k2], q2 = qA[k2];
            float c = cA[k2], s = sA[k2];
            float a1 = Ss[row*SPch+p2], b1 = Ss[row*SPch+q2];
            Ss[row*SPch+p2] = c*a1 - s*b1;  Ss[row*SPch+q2] = s*a1 + c*b1;
            float v1 = Vs[row*SPch+p2], v2 = Vs[row*SPch+q2];
            Vs[row*SPch+p2] = c*v1 - s*v2;  Vs[row*SPch+q2] = s*v1 + c*v2;
        }
        __syncthreads();
        {   // row rotations on S
            int k2 = tid >> 5, col = tid & 31;
            int p2 = pA[k2], q2 = qA[k2];
            float c = cA[k2], s = sA[k2];
            float a1 = Ss[p2*SPch+col], b1 = Ss[q2*SPch+col];
            Ss[p2*SPch+col] = c*a1 - s*b1;  Ss[q2*SPch+col] = s*a1 + c*b1;
        }
        __syncthreads();
    }

    if (tid == 0) {
        float ev[32];
        for (int i2 = 0; i2 < 32; i2++) ev[i2] = Ss[i2*SPch+i2];
        for (int j = 0; j < KT; j++) {
            int bi = 0; float bv = -3.0e38f;
            for (int i2 = 0; i2 < 32; i2++) if (ev[i2] > bv) { bv = ev[i2]; bi = i2; }
            idxS[j] = bi; ev[bi] = -3.0e38f;
        }
    }
    __syncthreads();
    if (tid < PP*UPch) {
        int k2 = tid % PP, j = tid / PP;
        Vsel[k2*UPch + j] = (j < KT) ? Vs[k2*SPch + idxS[j]] : 0.f;
    }
    __syncthreads();

    // U = Q * Vsel  (256 x 10)
    if (tid < 256) {
        float u[KT];
#pragma unroll
        for (int j = 0; j < KT; j++) u[j] = 0.f;
#pragma unroll 4
        for (int k2 = 0; k2 < PP; k2++) {
            float qv = Qs[tid*QP + k2];
#pragma unroll
            for (int j = 0; j < KT; j++) u[j] = fmaf(qv, Vsel[k2*UPch + j], u[j]);
        }
#pragma unroll
        for (int j = 0; j < KT; j++) Us[tid*UPch + j] = u[j];
    }
    __syncthreads();

    // C = U^T A  (10 x 256) split over halves, partials in Cs
    {
        float c[KT];
#pragma unroll
        for (int k = 0; k < KT; k++) c[k] = 0.f;
        int i0 = h * 128;
#pragma unroll 4
        for (int i = i0; i < i0 + 128; i++) {
            float a = __ldg(Ab + (size_t)i*NN + t);
#pragma unroll
            for (int k = 0; k < KT; k++) c[k] = fmaf(Us[i*UPch + k], a, c[k]);
        }
#pragma unroll
        for (int k = 0; k < KT; k++) Cs[h*2560 + k*NN + t] = c[k];
    }
    __syncthreads();

    // Pass 1: Tpnew = U*C, write out
    float creg[KT];
#pragma unroll
    for (int k = 0; k < KT; k++) creg[k] = Cs[k*NN + t] + Cs[2560 + k*NN + t];
    {
        int i0 = h * 128;
        for (int i = i0; i < i0 + 128; i++) {
            float tp = 0.f;
#pragma unroll
            for (int k = 0; k < KT; k++) tp = fmaf(Us[i*UPch + k], creg[k], tp);
            outTp[(size_t)i*NN + t] = tp;
        }
    }
    __syncthreads();

    // Diagonal averages of M = 2*Tpnew - Sp: one thread per diagonal.
    if (tid < 511) {
        int off = tid - 255;
        float s = 0.f;
        for (int i = 0; i < NN; i++) {
            int j = i + off;
            if ((unsigned)j < NN) {
                float tp = outTp[(size_t)i*NN + j];
                float sp = Spb[(size_t)i*NN + j];
                s += 2.f*tp - sp;
            }
        }
        int cnt = NN - abs(off);
        Av[tid] = s / (float)cnt;
    }
    __syncthreads();

    // Pass 2: Spnew = Sp - Tpnew + avg[diag]  (recompute tp from registers)
    {
        int i0 = h * 128;
        for (int i = i0; i < i0 + 128; i++) {
            float tp = 0.f;
#pragma unroll
            for (int k = 0; k < KT; k++) tp = fmaf(Us[i*UPch + k], creg[k], tp);
            outSp[(size_t)i*NN + t] =
                __ldg(Spb + (size_t)i*NN + t) - tp + Av[t - i + 255];
        }
    }
}

extern "C" void kernel_launch(void* const* d_in, const int* in_sizes, int n_in,
                              void* d_out, int out_size) {
    const float* T  = (const float*)d_in[0];
    const float* Tp = (const float*)d_in[1];
    const float* Sp = (const float*)d_in[2];
    const float* w1 = (const float*)d_in[3];
    const float* w2 = (const float*)d_in[4];
    const float* w3 = (const float*)d_in[5];
    const float* w4 = (const float*)d_in[6];
    float* out = (float*)d_out;
    cudaFuncSetAttribute(cadzow_kernel,
                         cudaFuncAttributeMaxDynamicSharedMemorySize, SMEM_BYTES);
    cadzow_kernel<<<NB, NT, SMEM_BYTES>>>(T, Tp, Sp, w1, w2, w3, w4, out);
}

// round 17
// speedup vs baseline: 1.6969x; 1.0300x over previous
#include <cuda_runtime.h>
#include <cuda_bf16.h>
#include <math.h>

#define NB 128
#define NN 256
#define NSQ (NN*NN)
#define PP 32
#define KT 10
#define NSTAGE 7          // 7 stages x 4 matvecs = 28 power iterations
#define SWEEPS 7
#define QP 36
#define SPch 33
#define UPch 12
#define NT 512

__device__ float g_A[(size_t)NB * NSQ];
__device__ float g_G[(size_t)NB * NSQ];

#define O_QS   0
#define O_YS   9216
#define O_PB   18432
#define O_SS   19584
#define O_VS   20640
#define O_VSEL 21696
#define O_US   22080
#define O_CS   25152
#define O_AVG  30272
#define O_MISC 30784
#define O_SG   30912            /* 2 x 4096 floats: staged G rows (16-row groups) */
#define SMEM_FLOATS (O_SG + 8192)
#define SMEM_BYTES (SMEM_FLOATS*4)   /* 156,416 B */

// packed fp32x2 FMA: d = a*b + d (two independent fp32 lanes, exact fp32 rounding)
#define FMA2(d, a, b) asm("fma.rn.f32x2 %0, %1, %2, %0;" : "+l"(d) : "l"(a), "l"(b))

__device__ __forceinline__ float2 unpack2(unsigned long long v) {
    float lo, hi;
    asm("mov.b64 {%0, %1}, %2;" : "=f"(lo), "=f"(hi) : "l"(v));
    return make_float2(lo, hi);
}

// Y = G * Qin (256x256 * 256x32). thread (t,h) -> Y[t][h*16..h*16+16).
// G rows streamed through double-buffered smem (16-row groups); inner loop uses
// packed fma.rn.f32x2 (8 FFMA2 per k instead of 16 FFMA -> half FFMA-pipe cost).
__device__ __forceinline__ void mv512s(const float* __restrict__ Gb,
                                       const float* __restrict__ Qin,
                                       float* __restrict__ Yout,
                                       float* __restrict__ sG,
                                       int t, int h, int tid)
{
    unsigned long long acc[8];
#pragma unroll
    for (int j = 0; j < 8; j++) acc[j] = 0ull;
    const float* qb = Qin + h * 16;

    // prologue: rows 0..15 -> buffer 0 (512 threads x 2 float4 = 4096 floats)
    ((float4*)sG)[tid]       = __ldg((const float4*)Gb + tid);
    ((float4*)sG)[tid + 512] = __ldg((const float4*)Gb + tid + 512);
    __syncthreads();

    for (int grp = 0; grp < 16; grp++) {
        const float* cur = sG + (grp & 1) * 4096;
        float*       nxt = sG + ((grp & 1) ^ 1) * 4096;
        float4 p0, p1;
        const bool hp = (grp + 1 < 16);
        if (hp) {
            const float4* src = (const float4*)(Gb + (size_t)(grp + 1) * 4096);
            p0 = __ldg(src + tid);
            p1 = __ldg(src + tid + 512);
        }
#pragma unroll
        for (int u = 0; u < 16; u++) {
            float g = cur[u*NN + t];
            unsigned long long gg;
            asm("mov.b64 %0, {%1, %1};" : "=l"(gg) : "r"(__float_as_uint(g)));
            const ulonglong2* qr = (const ulonglong2*)(qb + (grp*16 + u) * QP);
            ulonglong2 qa = qr[0], qc = qr[1];
            FMA2(acc[0], gg, qa.x); FMA2(acc[1], gg, qa.y);
            FMA2(acc[2], gg, qc.x); FMA2(acc[3], gg, qc.y);
            ulonglong2 qe = qr[2], qg = qr[3];
            FMA2(acc[4], gg, qe.x); FMA2(acc[5], gg, qe.y);
            FMA2(acc[6], gg, qg.x); FMA2(acc[7], gg, qg.y);
        }
        if (hp) { ((float4*)nxt)[tid] = p0; ((float4*)nxt)[tid + 512] = p1; }
        __syncthreads();
    }
#pragma unroll
    for (int c4 = 0; c4 < 4; c4++) {
        float2 a = unpack2(acc[c4*2]), b2 = unpack2(acc[c4*2 + 1]);
        *(float4*)(Yout + t*QP + h*16 + c4*4) = make_float4(a.x, a.y, b2.x, b2.y);
    }
}

// S[a][b] = sum_k X[k][a]*Y[k][b] ; 512 threads, 2 outputs each (packed FMA2)
__device__ __forceinline__ void gram512(const float* __restrict__ X,
                                        const float* __restrict__ Y,
                                        float* __restrict__ S, int tid)
{
    int a = tid >> 4, b2 = (tid & 15) << 1;
    unsigned long long s = 0ull;
#pragma unroll 4
    for (int k = 0; k < NN; k++) {
        float xa = X[k*QP + a];
        unsigned long long gg;
        asm("mov.b64 %0, {%1, %1};" : "=l"(gg) : "r"(__float_as_uint(xa)));
        unsigned long long yb = *(const unsigned long long*)(Y + k*QP + b2);
        FMA2(s, gg, yb);
    }
    float2 r = unpack2(s);
    S[a*SPch + b2]     = r.x;
    S[a*SPch + b2 + 1] = r.y;
}

__device__ __forceinline__ void cholqr512(float* __restrict__ Q, float* __restrict__ S,
                                          float* __restrict__ dinv, int tid)
{
    gram512(Q, Q, S, tid);
    __syncthreads();
    if (tid < 32) {
        int i = tid;
        for (int j = 0; j < 32; j++) {
            float d = sqrtf(fmaxf(S[j*SPch+j], 1e-30f));
            float lij = (i > j) ? S[i*SPch+j] / d : 0.f;
            __syncwarp();
            if (i == j) { S[j*SPch+j] = d; dinv[j] = 1.0f/d; }
            if (i >  j) S[i*SPch+j] = lij;
            __syncwarp();
            if (i > j)
                for (int c = j+1; c <= i; c++)
                    S[i*SPch+c] -= lij * S[c*SPch+j];
            __syncwarp();
        }
    }
    __syncthreads();
    if (tid < 256) {
        float q[32];
#pragma unroll
        for (int j = 0; j < 32; j++) {
            float v = Q[tid*QP + j];
#pragma unroll
            for (int i2 = 0; i2 < j; i2++) v -= q[i2] * S[j*SPch + i2];
            q[j] = v * dinv[j];
        }
#pragma unroll
        for (int j4 = 0; j4 < 8; j4++)
            *(float4*)(Q + tid*QP + j4*4) =
                make_float4(q[j4*4], q[j4*4+1], q[j4*4+2], q[j4*4+3]);
    }
    __syncthreads();
}

__global__ void __launch_bounds__(NT, 1)
cadzow_kernel(const float* __restrict__ Tin, const float* __restrict__ Tpin,
              const float* __restrict__ Spin, const float* __restrict__ w1,
              const float* __restrict__ w2,  const float* __restrict__ w3,
              const float* __restrict__ w4,  float* __restrict__ out)
{
    extern __shared__ float sm[];
    const int tid = threadIdx.x;
    const int b = blockIdx.x;
    const int t = tid & 255;
    const int h = tid >> 8;

    float* Qs = sm + O_QS;   float* Ys = sm + O_YS;  float* Pc = sm + O_YS;
    float* Pb = sm + O_PB;   float* Ss = sm + O_SS;  float* Vs = sm + O_VS;
    float* Vsel = sm + O_VSEL; float* Us = sm + O_US; float* Cs = sm + O_CS;
    float* Av = sm + O_AVG;  float* sG = sm + O_SG;
    float* cA = sm + O_MISC; float* sA = cA + 16;
    int* pA = (int*)(sA + 16); int* qA = pA + 16; int* idxS = qA + 16;
    float* dinv = (float*)(idxS + 16);

    float* Ab = g_A + (size_t)b * NSQ;
    float* Gb = g_G + (size_t)b * NSQ;
    const float* Tb  = Tin  + (size_t)b * NSQ;
    const float* Tpb = Tpin + (size_t)b * NSQ;
    const float* Spb = Spin + (size_t)b * NSQ;
    float* outT  = out + (size_t)b * NSQ;
    float* outTp = out + (size_t)NB * NSQ     + (size_t)b * NSQ;
    float* outSp = out + 2*(size_t)NB * NSQ   + (size_t)b * NSQ;

    // ---- Phase A: A = diag(w1)Sp + diag(w2)Tp + w4.*Tp + w3.*T ; copy T ----
    for (int i = tid; i < NSQ; i += NT) {
        int r = i >> 8;
        float tv = Tb[i];
        Ab[i] = w1[r*257]*Spb[i] + (w2[r*257] + w4[i])*Tpb[i] + w3[i]*tv;
        outT[i] = tv;
    }
    __syncthreads();

    // ---- Phase B: G = A A^T ; thread (t,h) computes G[t][jb*32 + h*16 .. +16) ----
    for (int jb = 0; jb < 8; jb++) {
        float acc[16];
#pragma unroll
        for (int j = 0; j < 16; j++) acc[j] = 0.f;
        for (int kb = 0; kb < 8; kb++) {
            __syncthreads();
            for (int i = tid; i < NN*8; i += NT) {
                int r = i >> 3, c4 = i & 7;
                *(float4*)(Pc + r*QP + c4*4) =
                    *(const float4*)(Ab + r*NN + kb*PP + c4*4);
            }
            if (tid < 256) {
                int j = tid >> 3, c4 = tid & 7;
                *(float4*)(Pb + j*QP + c4*4) =
                    *(const float4*)(Ab + (jb*PP + j)*NN + kb*PP + c4*4);
            }
            __syncthreads();
#pragma unroll
            for (int c4 = 0; c4 < 8; c4++) {
                float4 own = *(const float4*)(Pc + t*QP + c4*4);
#pragma unroll
                for (int j = 0; j < 16; j++) {
                    float4 bb = *(const float4*)(Pb + (h*16 + j)*QP + c4*4);
                    acc[j] += own.x*bb.x + own.y*bb.y + own.z*bb.z + own.w*bb.w;
                }
            }
        }
#pragma unroll
        for (int j4 = 0; j4 < 4; j4++)
            *(float4*)(Gb + (size_t)t*NN + jb*PP + h*16 + j4*4) =
                make_float4(acc[j4*4], acc[j4*4+1], acc[j4*4+2], acc[j4*4+3]);
    }
    __syncthreads();

    // ---- Phase C: deterministic pseudo-random Q init ----
    for (int i = tid; i < NN*PP; i += NT) {
        int k = i >> 5, j = i & 31;
        unsigned hh = (unsigned)(k*1664525 + j*1013904223 + 12345);
        hh ^= hh>>16; hh *= 0x7feb352du; hh ^= hh>>15; hh *= 0x846ca68bu; hh ^= hh>>16;
        Qs[k*QP + j] = (float)(hh & 0xFFFFFFu) * (1.0f/8388608.0f) - 1.0f;
    }
    __syncthreads();

    // ---- Phase D: 7 x (4 matvecs + CholQR) = 28 power iterations ----
    for (int st = 0; st < NSTAGE; st++) {
        mv512s(Gb, Qs, Ys, sG, t, h, tid); __syncthreads();
        mv512s(Gb, Ys, Qs, sG, t, h, tid); __syncthreads();
        mv512s(Gb, Qs, Ys, sG, t, h, tid); __syncthreads();
        mv512s(Gb, Ys, Qs, sG, t, h, tid); __syncthreads();
        cholqr512(Qs, Ss, dinv, tid);
    }
    mv512s(Gb, Qs, Ys, sG, t, h, tid);   // final Y = G*Q for Rayleigh-Ritz
    __syncthreads();

    // ---- Phase E: Rayleigh-Ritz ----
    gram512(Qs, Ys, Ss, tid);
    __syncthreads();
    for (int i = tid; i < 1024; i += NT) {
        int a2 = i >> 5, b2 = i & 31;
        Vs[a2*SPch + b2] = (a2 == b2) ? 1.0f : 0.f;
        if (a2 < b2) {
            float m = 0.5f*(Ss[a2*SPch+b2] + Ss[b2*SPch+a2]);
            Ss[a2*SPch+b2] = m; Ss[b2*SPch+a2] = m;
        }
    }
    __syncthreads();

    for (int sw = 0; sw < SWEEPS; sw++)
    for (int r = 0; r < 31; r++) {
        if (tid < 16) {
            int p2, q2;
            if (tid == 0) { p2 = 31; q2 = r % 31; }
            else { p2 = (r + tid) % 31; q2 = (r + 31 - tid) % 31; }
            float spp = Ss[p2*SPch+p2], sqq = Ss[q2*SPch+q2], spq = Ss[p2*SPch+q2];
            float c = 1.f, s = 0.f;
            if (fabsf(spq) > 1e-12f*(fabsf(spp)+fabsf(sqq)) + 1e-30f) {
                float tau = (sqq - spp) / (2.f*spq);
                float t2 = (tau >= 0.f ? 1.f : -1.f) / (fabsf(tau) + sqrtf(1.f + tau*tau));
                c = rsqrtf(1.f + t2*t2); s = t2*c;
            }
            cA[tid] = c; sA[tid] = s; pA[tid] = p2; qA[tid] = q2;
        }
        __syncthreads();
        {   // column rotations on S and V (one element per thread)
            int k2 = tid >> 5, row = tid & 31;
            int p2 = pA[k2], q2 = qA[k2];
            float c = cA[k2], s = sA[k2];
            float a1 = Ss[row*SPch+p2], b1 = Ss[row*SPch+q2];
            Ss[row*SPch+p2] = c*a1 - s*b1;  Ss[row*SPch+q2] = s*a1 + c*b1;
            float v1 = Vs[row*SPch+p2], v2 = Vs[row*SPch+q2];
            Vs[row*SPch+p2] = c*v1 - s*v2;  Vs[row*SPch+q2] = s*v1 + c*v2;
        }
        __syncthreads();
        {   // row rotations on S
            int k2 = tid >> 5, col = tid & 31;
            int p2 = pA[k2], q2 = qA[k2];
            float c = cA[k2], s = sA[k2];
            float a1 = Ss[p2*SPch+col], b1 = Ss[q2*SPch+col];
            Ss[p2*SPch+col] = c*a1 - s*b1;  Ss[q2*SPch+col] = s*a1 + c*b1;
        }
        __syncthreads();
    }

    if (tid == 0) {
        float ev[32];
        for (int i2 = 0; i2 < 32; i2++) ev[i2] = Ss[i2*SPch+i2];
        for (int j = 0; j < KT; j++) {
            int bi = 0; float bv = -3.0e38f;
            for (int i2 = 0; i2 < 32; i2++) if (ev[i2] > bv) { bv = ev[i2]; bi = i2; }
            idxS[j] = bi; ev[bi] = -3.0e38f;
        }
    }
    __syncthreads();
    if (tid < PP*UPch) {
        int k2 = tid % PP, j = tid / PP;
        Vsel[k2*UPch + j] = (j < KT) ? Vs[k2*SPch + idxS[j]] : 0.f;
    }
    __syncthreads();

    // U = Q * Vsel  (256 x 10)
    if (tid < 256) {
        float u[KT];
#pragma unroll
        for (int j = 0; j < KT; j++) u[j] = 0.f;
#pragma unroll 4
        for (int k2 = 0; k2 < PP; k2++) {
            float qv = Qs[tid*QP + k2];
#pragma unroll
            for (int j = 0; j < KT; j++) u[j] = fmaf(qv, Vsel[k2*UPch + j], u[j]);
        }
#pragma unroll
        for (int j = 0; j < KT; j++) Us[tid*UPch + j] = u[j];
    }
    __syncthreads();

    // C = U^T A  (10 x 256) split over halves, partials in Cs
    {
        float c[KT];
#pragma unroll
        for (int k = 0; k < KT; k++) c[k] = 0.f;
        int i0 = h * 128;
#pragma unroll 4
        for (int i = i0; i < i0 + 128; i++) {
            float a = __ldg(Ab + (size_t)i*NN + t);
#pragma unroll
            for (int k = 0; k < KT; k++) c[k] = fmaf(Us[i*UPch + k], a, c[k]);
        }
#pragma unroll
        for (int k = 0; k < KT; k++) Cs[h*2560 + k*NN + t] = c[k];
    }
    __syncthreads();

    // Pass 1: Tpnew = U*C, write out
    float creg[KT];
#pragma unroll
    for (int k = 0; k < KT; k++) creg[k] = Cs[k*NN + t] + Cs[2560 + k*NN + t];
    {
        int i0 = h * 128;
        for (int i = i0; i < i0 + 128; i++) {
            float tp = 0.f;
#pragma unroll
            for (int k = 0; k < KT; k++) tp = fmaf(Us[i*UPch + k], creg[k], tp);
            outTp[(size_t)i*NN + t] = tp;
        }
    }
    __syncthreads();

    // Diagonal averages of M = 2*Tpnew - Sp: one thread per diagonal.
    if (tid < 511) {
        int off = tid - 255;
        float s = 0.f;
        for (int i = 0; i < NN; i++) {
            int j = i + off;
            if ((unsigned)j < NN) {
                float tp = outTp[(size_t)i*NN + j];
                float sp = Spb[(size_t)i*NN + j];
                s += 2.f*tp - sp;
            }
        }
        int cnt = NN - abs(off);
        Av[tid] = s / (float)cnt;
    }
    __syncthreads();

    // Pass 2: Spnew = Sp - Tpnew + avg[diag]  (recompute tp from registers)
    {
        int i0 = h * 128;
        for (int i = i0; i < i0 + 128; i++) {
            float tp = 0.f;
#pragma unroll
            for (int k = 0; k < KT; k++) tp = fmaf(Us[i*UPch + k], creg[k], tp);
            outSp[(size_t)i*NN + t] =
                __ldg(Spb + (size_t)i*NN + t) - tp + Av[t - i + 255];
        }
    }
}

extern "C" void kernel_launch(void* const* d_in, const int* in_sizes, int n_in,
                              void* d_out, int out_size) {
    const float* T  = (const float*)d_in[0];
    const float* Tp = (const float*)d_in[1];
    const float* Sp = (const float*)d_in[2];
    const float* w1 = (const float*)d_in[3];
    const float* w2 = (const float*)d_in[4];
    const float* w3 = (const float*)d_in[5];
    const float* w4 = (const float*)d_in[6];
    float* out = (float*)d_out;
    cudaFuncSetAttribute(cadzow_kernel,
                         cudaFuncAttributeMaxDynamicSharedMemorySize, SMEM_BYTES);
    cadzow_kernel<<<NB, NT, SMEM_BYTES>>>(T, Tp, Sp, w1, w2, w3, w4, out);
}